// round 15
// baseline (speedup 1.0000x reference)
#include <cuda_runtime.h>
#include <cuda_bf16.h>
#include <cstdint>

// Problem constants
#define B_  4
#define L_  2048
#define D_  1024
#define H_  16
#define HD_ 64
#define NT_ (B_ * L_)          // 8192 tokens
#define BH_ (B_ * H_)          // 64 head-streams

// k-interleaved bf16 {hi,lo} splits: per k-pair, [hi_u32, lo_u32].
// Row of K bf16 elems -> K u32 (same bytes as fp32 original).
__device__ uint32_t g_xI[(size_t)NT_ * D_];
__device__ uint32_t g_wqI[(size_t)3 * D_ * D_];
__device__ uint32_t g_woI[(size_t)D_ * D_];
__device__ uint32_t g_ctxI[(size_t)NT_ * D_];
// Attention operands: q/k planar bf16 [bh][l][d]; v^T fp32 tf32-rounded [bh][d][l]
__device__ __nv_bfloat16 g_qh[(size_t)BH_ * L_ * HD_];
__device__ __nv_bfloat16 g_ql[(size_t)BH_ * L_ * HD_];
__device__ __nv_bfloat16 g_kh[(size_t)BH_ * L_ * HD_];
__device__ __nv_bfloat16 g_kl[(size_t)BH_ * L_ * HD_];
__device__ float g_vt[(size_t)BH_ * HD_ * L_];

__device__ __forceinline__ uint32_t smem_u32(const void* p) {
    uint32_t a;
    asm("{ .reg .u64 t; cvta.to.shared.u64 t, %1; cvt.u32.u64 %0, t; }"
        : "=r"(a) : "l"(p));
    return a;
}
__device__ __forceinline__ void cp_async16(uint32_t saddr, const void* gaddr) {
    asm volatile("cp.async.cg.shared.global [%0], [%1], 16;"
                 :: "r"(saddr), "l"(gaddr) : "memory");
}
__device__ __forceinline__ void cp_commit() {
    asm volatile("cp.async.commit_group;" ::: "memory");
}
__device__ __forceinline__ void cp_wait1() {
    asm volatile("cp.async.wait_group 1;" ::: "memory");
}
__device__ __forceinline__ void cp_wait0() {
    asm volatile("cp.async.wait_group 0;" ::: "memory");
}

__device__ __forceinline__ void mma_tf32(float& c0, float& c1, float& c2, float& c3,
                                         uint32_t a0, uint32_t a1, uint32_t a2, uint32_t a3,
                                         uint32_t b0, uint32_t b1) {
    asm volatile(
        "mma.sync.aligned.m16n8k8.row.col.f32.tf32.tf32.f32 "
        "{%0,%1,%2,%3}, {%4,%5,%6,%7}, {%8,%9}, {%0,%1,%2,%3};"
        : "+f"(c0), "+f"(c1), "+f"(c2), "+f"(c3)
        : "r"(a0), "r"(a1), "r"(a2), "r"(a3), "r"(b0), "r"(b1));
}
__device__ __forceinline__ void mma_bf16(float& c0, float& c1, float& c2, float& c3,
                                         uint32_t a0, uint32_t a1, uint32_t a2, uint32_t a3,
                                         uint32_t b0, uint32_t b1) {
    asm volatile(
        "mma.sync.aligned.m16n8k16.row.col.f32.bf16.bf16.f32 "
        "{%0,%1,%2,%3}, {%4,%5,%6,%7}, {%8,%9}, {%0,%1,%2,%3};"
        : "+f"(c0), "+f"(c1), "+f"(c2), "+f"(c3)
        : "r"(a0), "r"(a1), "r"(a2), "r"(a3), "r"(b0), "r"(b1));
}

__device__ __forceinline__ float tf32_rna(float f) {
    uint32_t h;
    asm("cvt.rna.tf32.f32 %0, %1;" : "=r"(h) : "f"(f));
    return __uint_as_float(h);
}
__device__ __forceinline__ uint32_t pack_hi(float a, float b) {
    __nv_bfloat162 v(__float2bfloat16(a), __float2bfloat16(b));
    return *(uint32_t*)&v;
}

// ---------------------------------------------------------------------------
// Prep: fp32 -> k-interleaved bf16 {hi,lo}. out uint4 = {hi01, lo01, hi23, lo23}
// ---------------------------------------------------------------------------
__global__ void split_bf16i_kernel(const float4* __restrict__ in,
                                   uint4* __restrict__ out, int n4)
{
    int i = blockIdx.x * blockDim.x + threadIdx.x;
    if (i >= n4) return;
    float4 v = in[i];
    __nv_bfloat16 h0 = __float2bfloat16(v.x);
    __nv_bfloat16 h1 = __float2bfloat16(v.y);
    __nv_bfloat16 h2 = __float2bfloat16(v.z);
    __nv_bfloat16 h3 = __float2bfloat16(v.w);
    __nv_bfloat162 hi01(h0, h1), hi23(h2, h3);
    __nv_bfloat162 lo01(__float2bfloat16(v.x - __bfloat162float(h0)),
                        __float2bfloat16(v.y - __bfloat162float(h1)));
    __nv_bfloat162 lo23(__float2bfloat16(v.z - __bfloat162float(h2)),
                        __float2bfloat16(v.w - __bfloat162float(h3)));
    out[i] = make_uint4(*(uint32_t*)&hi01, *(uint32_t*)&lo01,
                        *(uint32_t*)&hi23, *(uint32_t*)&lo23);
}

// ---------------------------------------------------------------------------
// bf16x3 GEMM on k-interleaved operands. 8 warps, 64x32 warp tile, 2 CTAs/SM.
// Fragment hi+lo pairs load as single LDS.64 (half the LDS instructions).
// mode 0: fp32 store; mode 1: QKV scatter (q/k planar bf16, v^T tf32 fp32).
// ---------------------------------------------------------------------------
#define PADU 40                          // u32 per smem row (32 data + 8 pad)
#define PLANEI (128 * PADU)              // u32 per matrix tile
#define STAGEI (2 * PLANEI)              // A + B
#define GK_SMEM_BYTES (2 * STAGEI * 4)   // 81920 B

__global__ __launch_bounds__(256, 2) void gemm_bf16_kernel(
    const uint32_t* __restrict__ AI, const uint32_t* __restrict__ BI,
    float* __restrict__ C,
    __nv_bfloat16* __restrict__ qh, __nv_bfloat16* __restrict__ ql,
    __nv_bfloat16* __restrict__ kh, __nv_bfloat16* __restrict__ kl,
    float* __restrict__ vo,
    int M, int N, int K, int mode)
{
    extern __shared__ uint32_t smu[];

    const int t    = threadIdx.x;
    const int wid  = t >> 5;
    const int lane = t & 31;
    const int g    = lane >> 2;
    const int c4   = lane & 3;
    const int m0   = blockIdx.y * 128;
    const int n0   = blockIdx.x * 128;
    const int wm   = (wid & 1) * 64;
    const int wn   = (wid >> 1) * 32;

    float acc[4][4][4] = {};
    const int nchunks = K >> 5;          // 32 bf16 = 32 u32 per row per chunk

    #define LOAD_CHUNK(cc)                                                    \
    {                                                                         \
        const int s_   = (cc) & 1;                                            \
        const int k0u_ = (cc) * 32;                                           \
        const uint32_t base_ = smem_u32(smu) + s_ * STAGEI * 4;               \
        _Pragma("unroll")                                                     \
        for (int u = 0; u < 8; u++) {                                         \
            const int pl  = u >> 2;                                           \
            const int rem = ((u & 3) << 8) + t;                               \
            const int row = rem >> 3;                                         \
            const int grp = rem & 7;                                          \
            const uint32_t* src = (pl == 0 ? AI : BI);                        \
            const int mr  = (pl == 0 ? m0 : n0) + row;                        \
            cp_async16(base_ + (pl * PLANEI + row * PADU + grp * 4) * 4,      \
                       src + (size_t)mr * K + k0u_ + grp * 4);                \
        }                                                                     \
        cp_commit();                                                          \
    }

    LOAD_CHUNK(0);

    for (int c = 0; c < nchunks; c++) {
        if (c + 1 < nchunks) {
            LOAD_CHUNK(c + 1);
            cp_wait1();
        } else {
            cp_wait0();
        }
        __syncthreads();

        const uint32_t* S  = smu + (c & 1) * STAGEI;
        const uint32_t* AU = S;
        const uint32_t* BU = S + PLANEI;

        #pragma unroll
        for (int kk = 0; kk < 32; kk += 16) {
            // u32 offset within row: kk + 2*c4 (pair idx kk/2 + c4)
            uint32_t ah[4][4], al[4][4], bhf[4][2], blf[4][2];
            #pragma unroll
            for (int mi = 0; mi < 4; mi++) {
                const uint32_t* p = AU + (wm + mi * 16 + g) * PADU + kk + 2 * c4;
                uint2 w0 = *(const uint2*)(p);
                uint2 w1 = *(const uint2*)(p + 8 * PADU);
                uint2 w2 = *(const uint2*)(p + 8);
                uint2 w3 = *(const uint2*)(p + 8 * PADU + 8);
                ah[mi][0] = w0.x; al[mi][0] = w0.y;
                ah[mi][1] = w1.x; al[mi][1] = w1.y;
                ah[mi][2] = w2.x; al[mi][2] = w2.y;
                ah[mi][3] = w3.x; al[mi][3] = w3.y;
            }
            #pragma unroll
            for (int ni = 0; ni < 4; ni++) {
                const uint32_t* p = BU + (wn + ni * 8 + g) * PADU + kk + 2 * c4;
                uint2 w0 = *(const uint2*)(p);
                uint2 w1 = *(const uint2*)(p + 8);
                bhf[ni][0] = w0.x; blf[ni][0] = w0.y;
                bhf[ni][1] = w1.x; blf[ni][1] = w1.y;
            }
            #pragma unroll
            for (int mi = 0; mi < 4; mi++)
                #pragma unroll
                for (int ni = 0; ni < 4; ni++)
                    mma_bf16(acc[mi][ni][0], acc[mi][ni][1],
                             acc[mi][ni][2], acc[mi][ni][3],
                             ah[mi][0], ah[mi][1], ah[mi][2], ah[mi][3],
                             blf[ni][0], blf[ni][1]);
            #pragma unroll
            for (int mi = 0; mi < 4; mi++)
                #pragma unroll
                for (int ni = 0; ni < 4; ni++)
                    mma_bf16(acc[mi][ni][0], acc[mi][ni][1],
                             acc[mi][ni][2], acc[mi][ni][3],
                             al[mi][0], al[mi][1], al[mi][2], al[mi][3],
                             bhf[ni][0], bhf[ni][1]);
            #pragma unroll
            for (int mi = 0; mi < 4; mi++)
                #pragma unroll
                for (int ni = 0; ni < 4; ni++)
                    mma_bf16(acc[mi][ni][0], acc[mi][ni][1],
                             acc[mi][ni][2], acc[mi][ni][3],
                             ah[mi][0], ah[mi][1], ah[mi][2], ah[mi][3],
                             bhf[ni][0], bhf[ni][1]);
        }
        __syncthreads();
    }
    #undef LOAD_CHUNK

    #pragma unroll
    for (int mi = 0; mi < 4; mi++) {
        #pragma unroll
        for (int half = 0; half < 2; half++) {
            const int m = m0 + wm + mi * 16 + g + half * 8;
            if (mode == 0) {
                #pragma unroll
                for (int ni = 0; ni < 4; ni++) {
                    int n = n0 + wn + ni * 8 + c4 * 2;
                    float2 v = half == 0
                        ? make_float2(acc[mi][ni][0], acc[mi][ni][1])
                        : make_float2(acc[mi][ni][2], acc[mi][ni][3]);
                    *(float2*)(C + (size_t)m * N + n) = v;
                }
            } else {
                const int b = m >> 11;
                const int l = m & 2047;
                #pragma unroll
                for (int ni = 0; ni < 4; ni++) {
                    int n     = n0 + wn + ni * 8 + c4 * 2;
                    int which = n >> 10;
                    int rem   = n & 1023;
                    int h     = rem >> 6;
                    int d     = rem & 63;
                    int bh_i  = b * H_ + h;
                    float v0 = half == 0 ? acc[mi][ni][0] : acc[mi][ni][2];
                    float v1 = half == 0 ? acc[mi][ni][1] : acc[mi][ni][3];
                    if (which == 2) {
                        size_t idx = ((size_t)bh_i * HD_ + d) * L_ + l;
                        vo[idx]      = tf32_rna(v0);
                        vo[idx + L_] = tf32_rna(v1);
                    } else {
                        size_t idx = ((size_t)bh_i * L_ + l) * HD_ + d;
                        __nv_bfloat16 h0 = __float2bfloat16(v0);
                        __nv_bfloat16 h1 = __float2bfloat16(v1);
                        __nv_bfloat162 hi2(h0, h1);
                        __nv_bfloat162 lo2(
                            __float2bfloat16(v0 - __bfloat162float(h0)),
                            __float2bfloat16(v1 - __bfloat162float(h1)));
                        if (which == 0) {
                            *(__nv_bfloat162*)(qh + idx) = hi2;
                            *(__nv_bfloat162*)(ql + idx) = lo2;
                        } else {
                            *(__nv_bfloat162*)(kh + idx) = hi2;
                            *(__nv_bfloat162*)(kl + idx) = lo2;
                        }
                    }
                }
            }
        }
    }
}

// ---------------------------------------------------------------------------
// Flash attention (R14): S=QK^T bf16x3, P*V 1xTF32, cp.async double-buffered
// K/V, 2 CTAs/SM. Epilogue writes ctx k-interleaved for gemm-3.
// ---------------------------------------------------------------------------
#define KPAD 72
#define APAD 68
#define KPLANE (64 * KPAD)
#define VPLANE (64 * APAD)
#define ATT_STAGE_BYTES (2 * KPLANE * 2 + VPLANE * 4)        // 35840 B
#define ATT_SMEM_BYTES (2 * KPLANE * 2 + VPLANE * 4 \
                        + 2 * ATT_STAGE_BYTES)               // 107520 B

__global__ __launch_bounds__(128, 2) void attn_tc_kernel(
    const __nv_bfloat16* __restrict__ qh, const __nv_bfloat16* __restrict__ ql,
    const __nv_bfloat16* __restrict__ kh, const __nv_bfloat16* __restrict__ kl,
    const float* __restrict__ vt, uint32_t* __restrict__ ctxI)
{
    const int qt = (int)gridDim.x - 1 - (int)blockIdx.x;
    const int bh = blockIdx.y;

    extern __shared__ char smc[];
    __nv_bfloat16* Qh = (__nv_bfloat16*)smc;
    __nv_bfloat16* Ql = Qh + KPLANE;
    float* Ss = (float*)(Ql + KPLANE);
    char*  stage_base = (char*)(Ss + VPLANE);

    const int t    = threadIdx.x;
    const int w    = t >> 5;
    const int lane = t & 31;
    const int g    = lane >> 2;
    const int c4   = lane & 3;
    const int q0   = w * 16;

    const __nv_bfloat16* Qhg = qh + ((size_t)bh * L_ + (size_t)qt * 64) * HD_;
    const __nv_bfloat16* Qlg = ql + ((size_t)bh * L_ + (size_t)qt * 64) * HD_;
    const __nv_bfloat16* Khg = kh + ((size_t)bh * L_) * HD_;
    const __nv_bfloat16* Klg = kl + ((size_t)bh * L_) * HD_;
    const float*         Vg  = vt + ((size_t)bh * HD_) * L_;

    #pragma unroll
    for (int u = 0; u < 4; u++) {
        int idx = t + u * 128;
        int row = idx >> 3;
        int cg  = idx & 7;
        *(uint4*)&Qh[row * KPAD + cg * 8] =
            *(const uint4*)(Qhg + (size_t)row * HD_ + cg * 8);
        *(uint4*)&Ql[row * KPAD + cg * 8] =
            *(const uint4*)(Qlg + (size_t)row * HD_ + cg * 8);
    }

    #define LOAD_TILE(kt_)                                                    \
    {                                                                         \
        const uint32_t sb_ = smem_u32(stage_base) +                           \
                             ((kt_) & 1) * ATT_STAGE_BYTES;                   \
        const uint32_t sKh_ = sb_;                                            \
        const uint32_t sKl_ = sb_ + KPLANE * 2;                               \
        const uint32_t sV_  = sb_ + 2 * KPLANE * 2;                           \
        _Pragma("unroll")                                                     \
        for (int u = 0; u < 4; u++) {                                         \
            int idx = t + u * 128;                                            \
            int row = idx >> 3;                                               \
            int cg  = idx & 7;                                                \
            cp_async16(sKh_ + (row * KPAD + cg * 8) * 2,                      \
                       Khg + ((size_t)((kt_) * 64 + row)) * HD_ + cg * 8);    \
            cp_async16(sKl_ + (row * KPAD + cg * 8) * 2,                      \
                       Klg + ((size_t)((kt_) * 64 + row)) * HD_ + cg * 8);    \
        }                                                                     \
        _Pragma("unroll")                                                     \
        for (int u = 0; u < 8; u++) {                                         \
            int idx = t + u * 128;                                            \
            int row = idx >> 4;                                               \
            int cg  = idx & 15;                                               \
            cp_async16(sV_ + (row * APAD + cg * 4) * 4,                       \
                       Vg + (size_t)row * L_ + (kt_) * 64 + cg * 4);          \
        }                                                                     \
        cp_commit();                                                          \
    }

    LOAD_TILE(0);

    float m0r = -1.0e30f, m1r = -1.0e30f;
    float l0r = 0.0f,     l1r = 0.0f;
    float oacc[8][4] = {};

    for (int kt = 0; kt <= qt; kt++) {
        __syncthreads();

        if (kt + 1 <= qt) {
            LOAD_TILE(kt + 1);
            cp_wait1();
        } else {
            cp_wait0();
        }
        __syncthreads();

        const char* sb = stage_base + (kt & 1) * ATT_STAGE_BYTES;
        const uint32_t* KhU = (const uint32_t*)sb;
        const uint32_t* KlU = KhU + KPLANE / 2;
        const float*    Vts = (const float*)(sb + 2 * KPLANE * 2);

        float sacc[8][4] = {};
        const uint32_t* QhU = (const uint32_t*)Qh;
        const uint32_t* QlU = (const uint32_t*)Ql;
        #pragma unroll
        for (int kk = 0; kk < 64; kk += 16) {
            const int ko2 = (kk >> 1) + c4;
            uint32_t ah[4], al[4], kbh[8][2], kbl[8][2];
            {
                const int r = (q0 + g) * 36 + ko2;
                ah[0] = QhU[r];          al[0] = QlU[r];
                ah[1] = QhU[r + 288];    al[1] = QlU[r + 288];
                ah[2] = QhU[r + 4];      al[2] = QlU[r + 4];
                ah[3] = QhU[r + 292];    al[3] = QlU[r + 292];
            }
            #pragma unroll
            for (int ni = 0; ni < 8; ni++) {
                const int r = (ni * 8 + g) * 36 + ko2;
                kbh[ni][0] = KhU[r];     kbl[ni][0] = KlU[r];
                kbh[ni][1] = KhU[r + 4]; kbl[ni][1] = KlU[r + 4];
            }
            #pragma unroll
            for (int ni = 0; ni < 8; ni++)
                mma_bf16(sacc[ni][0], sacc[ni][1], sacc[ni][2], sacc[ni][3],
                         ah[0], ah[1], ah[2], ah[3], kbl[ni][0], kbl[ni][1]);
            #pragma unroll
            for (int ni = 0; ni < 8; ni++)
                mma_bf16(sacc[ni][0], sacc[ni][1], sacc[ni][2], sacc[ni][3],
                         al[0], al[1], al[2], al[3], kbh[ni][0], kbh[ni][1]);
            #pragma unroll
            for (int ni = 0; ni < 8; ni++)
                mma_bf16(sacc[ni][0], sacc[ni][1], sacc[ni][2], sacc[ni][3],
                         ah[0], ah[1], ah[2], ah[3], kbh[ni][0], kbh[ni][1]);
        }

        const int qrow0 = qt * 64 + q0 + g;
        const int qrow1 = qrow0 + 8;
        #pragma unroll
        for (int ni = 0; ni < 8; ni++) {
            int col0 = kt * 64 + ni * 8 + c4 * 2;
            int col1 = col0 + 1;
            sacc[ni][0] = (col0 <= qrow0) ? sacc[ni][0] * 0.125f : -1.0e30f;
            sacc[ni][1] = (col1 <= qrow0) ? sacc[ni][1] * 0.125f : -1.0e30f;
            sacc[ni][2] = (col0 <= qrow1) ? sacc[ni][2] * 0.125f : -1.0e30f;
            sacc[ni][3] = (col1 <= qrow1) ? sacc[ni][3] * 0.125f : -1.0e30f;
        }

        float mx0 = -1.0e30f, mx1 = -1.0e30f;
        #pragma unroll
        for (int ni = 0; ni < 8; ni++) {
            mx0 = fmaxf(mx0, fmaxf(sacc[ni][0], sacc[ni][1]));
            mx1 = fmaxf(mx1, fmaxf(sacc[ni][2], sacc[ni][3]));
        }
        mx0 = fmaxf(mx0, __shfl_xor_sync(0xffffffffu, mx0, 1));
        mx0 = fmaxf(mx0, __shfl_xor_sync(0xffffffffu, mx0, 2));
        mx1 = fmaxf(mx1, __shfl_xor_sync(0xffffffffu, mx1, 1));
        mx1 = fmaxf(mx1, __shfl_xor_sync(0xffffffffu, mx1, 2));

        float mn0 = fmaxf(m0r, mx0);
        float mn1 = fmaxf(m1r, mx1);
        float corr0 = __expf(m0r - mn0);
        float corr1 = __expf(m1r - mn1);
        m0r = mn0; m1r = mn1;

        float sum0 = 0.0f, sum1 = 0.0f;
        #pragma unroll
        for (int ni = 0; ni < 8; ni++) {
            sacc[ni][0] = __expf(sacc[ni][0] - mn0); sum0 += sacc[ni][0];
            sacc[ni][1] = __expf(sacc[ni][1] - mn0); sum0 += sacc[ni][1];
            sacc[ni][2] = __expf(sacc[ni][2] - mn1); sum1 += sacc[ni][2];
            sacc[ni][3] = __expf(sacc[ni][3] - mn1); sum1 += sacc[ni][3];
        }
        sum0 += __shfl_xor_sync(0xffffffffu, sum0, 1);
        sum0 += __shfl_xor_sync(0xffffffffu, sum0, 2);
        sum1 += __shfl_xor_sync(0xffffffffu, sum1, 1);
        sum1 += __shfl_xor_sync(0xffffffffu, sum1, 2);
        l0r = l0r * corr0 + sum0;
        l1r = l1r * corr1 + sum1;

        #pragma unroll
        for (int ni = 0; ni < 8; ni++) {
            oacc[ni][0] *= corr0; oacc[ni][1] *= corr0;
            oacc[ni][2] *= corr1; oacc[ni][3] *= corr1;
        }

        #pragma unroll
        for (int ni = 0; ni < 8; ni++) {
            *(float2*)&Ss[(q0 + g    ) * APAD + ni * 8 + c4 * 2] =
                make_float2(tf32_rna(sacc[ni][0]), tf32_rna(sacc[ni][1]));
            *(float2*)&Ss[(q0 + g + 8) * APAD + ni * 8 + c4 * 2] =
                make_float2(tf32_rna(sacc[ni][2]), tf32_rna(sacc[ni][3]));
        }
        __syncwarp();

        const uint32_t* Pu = (const uint32_t*)Ss;
        const uint32_t* Vu = (const uint32_t*)Vts;
        #pragma unroll
        for (int kk = 0; kk < 64; kk += 8) {
            uint32_t a0, a1, a2, a3;
            {
                const uint32_t* base = Pu + (q0 + g) * APAD + kk + c4;
                a0 = base[0];
                a1 = base[8 * APAD];
                a2 = base[4];
                a3 = base[8 * APAD + 4];
            }
            #pragma unroll
            for (int ni = 0; ni < 8; ni++) {
                const uint32_t* base = Vu + (ni * 8 + g) * APAD + kk + c4;
                uint32_t b0 = base[0];
                uint32_t b1 = base[4];
                mma_tf32(oacc[ni][0], oacc[ni][1], oacc[ni][2], oacc[ni][3],
                         a0, a1, a2, a3, b0, b1);
            }
        }
    }
    #undef LOAD_TILE

    // ---- normalize + write ctx k-interleaved {hi_u32, lo_u32} ----
    const int b = bh >> 4;
    const int h = bh & 15;
    const float inv0 = 1.0f / l0r;
    const float inv1 = 1.0f / l1r;
    const int l0i = qt * 64 + q0 + g;
    const int l1i = l0i + 8;
    #pragma unroll
    for (int ni = 0; ni < 8; ni++) {
        int d = ni * 8 + c4 * 2;                 // even
        size_t i0 = (((size_t)b * L_ + l0i) * H_ + h) * HD_ + d;
        size_t i1 = (((size_t)b * L_ + l1i) * H_ + h) * HD_ + d;
        float o00 = oacc[ni][0] * inv0, o01 = oacc[ni][1] * inv0;
        float o10 = oacc[ni][2] * inv1, o11 = oacc[ni][3] * inv1;
        __nv_bfloat16 h00 = __float2bfloat16(o00);
        __nv_bfloat16 h01 = __float2bfloat16(o01);
        __nv_bfloat16 h10 = __float2bfloat16(o10);
        __nv_bfloat16 h11 = __float2bfloat16(o11);
        __nv_bfloat162 hi0(h00, h01), hi1(h10, h11);
        __nv_bfloat162 lo0(__float2bfloat16(o00 - __bfloat162float(h00)),
                           __float2bfloat16(o01 - __bfloat162float(h01)));
        __nv_bfloat162 lo1(__float2bfloat16(o10 - __bfloat162float(h10)),
                           __float2bfloat16(o11 - __bfloat162float(h11)));
        *(uint2*)(ctxI + i0) = make_uint2(*(uint32_t*)&hi0, *(uint32_t*)&lo0);
        *(uint2*)(ctxI + i1) = make_uint2(*(uint32_t*)&hi1, *(uint32_t*)&lo1);
    }
}

// ---------------------------------------------------------------------------
extern "C" void kernel_launch(void* const* d_in, const int* in_sizes, int n_in,
                              void* d_out, int out_size)
{
    const float* x     = (const float*)d_in[0];
    const float* W_qkv = (const float*)d_in[1];
    const float* W_out = (const float*)d_in[2];
    float* out = (float*)d_out;

    uint32_t *xI, *wqI, *woI, *cI;
    __nv_bfloat16 *qhp, *qlp, *khp, *klp;
    float *vtp;
    cudaGetSymbolAddress((void**)&xI,  g_xI);
    cudaGetSymbolAddress((void**)&wqI, g_wqI);
    cudaGetSymbolAddress((void**)&woI, g_woI);
    cudaGetSymbolAddress((void**)&cI,  g_ctxI);
    cudaGetSymbolAddress((void**)&qhp, g_qh);
    cudaGetSymbolAddress((void**)&qlp, g_ql);
    cudaGetSymbolAddress((void**)&khp, g_kh);
    cudaGetSymbolAddress((void**)&klp, g_kl);
    cudaGetSymbolAddress((void**)&vtp, g_vt);

    cudaFuncSetAttribute(gemm_bf16_kernel,
                         cudaFuncAttributeMaxDynamicSharedMemorySize, GK_SMEM_BYTES);
    cudaFuncSetAttribute(attn_tc_kernel,
                         cudaFuncAttributeMaxDynamicSharedMemorySize, ATT_SMEM_BYTES);

    // 0) k-interleaved bf16 splits of inputs
    split_bf16i_kernel<<<(NT_ * D_ / 4 + 255) / 256, 256>>>(
        (const float4*)x, (uint4*)xI, NT_ * D_ / 4);
    split_bf16i_kernel<<<(3 * D_ * D_ / 4 + 255) / 256, 256>>>(
        (const float4*)W_qkv, (uint4*)wqI, 3 * D_ * D_ / 4);
    split_bf16i_kernel<<<(D_ * D_ / 4 + 255) / 256, 256>>>(
        (const float4*)W_out, (uint4*)woI, D_ * D_ / 4);

    // 1) QKV projection (bf16x3) -> q/k planar bf16, v^T tf32 fp32
    gemm_bf16_kernel<<<dim3(3 * D_ / 128, NT_ / 128), 256, GK_SMEM_BYTES>>>(
        xI, wqI, nullptr, qhp, qlp, khp, klp, vtp, NT_, 3 * D_, D_, 1);

    // 2) causal flash attention -> ctx k-interleaved
    attn_tc_kernel<<<dim3(L_ / 64, BH_), 128, ATT_SMEM_BYTES>>>(
        qhp, qlp, khp, klp, vtp, cI);

    // 3) output projection (bf16x3)
    gemm_bf16_kernel<<<dim3(D_ / 128, NT_ / 128), 256, GK_SMEM_BYTES>>>(
        cI, woI, out, nullptr, nullptr, nullptr, nullptr, nullptr,
        NT_, D_, D_, 0);
}

// round 16
// speedup vs baseline: 1.0719x; 1.0719x over previous
#include <cuda_runtime.h>
#include <cuda_bf16.h>
#include <cstdint>

// Problem constants
#define B_  4
#define L_  2048
#define D_  1024
#define H_  16
#define HD_ 64
#define NT_ (B_ * L_)          // 8192 tokens
#define BH_ (B_ * H_)          // 64 head-streams

// Planar bf16 {hi,lo} splits
__device__ __nv_bfloat16 g_xh[(size_t)NT_ * D_];
__device__ __nv_bfloat16 g_xl[(size_t)NT_ * D_];
__device__ __nv_bfloat16 g_wqh[(size_t)3 * D_ * D_];
__device__ __nv_bfloat16 g_wql[(size_t)3 * D_ * D_];
__device__ __nv_bfloat16 g_woh[(size_t)D_ * D_];
__device__ __nv_bfloat16 g_wol[(size_t)D_ * D_];
__device__ __nv_bfloat16 g_ctxh[(size_t)NT_ * D_];
__device__ __nv_bfloat16 g_ctxl[(size_t)NT_ * D_];
// Attention operands: q/k planar bf16 [bh][l][d]; v^T fp32 tf32-rounded [bh][d][l]
__device__ __nv_bfloat16 g_qh[(size_t)BH_ * L_ * HD_];
__device__ __nv_bfloat16 g_ql[(size_t)BH_ * L_ * HD_];
__device__ __nv_bfloat16 g_kh[(size_t)BH_ * L_ * HD_];
__device__ __nv_bfloat16 g_kl[(size_t)BH_ * L_ * HD_];
__device__ float g_vt[(size_t)BH_ * HD_ * L_];

__device__ __forceinline__ uint32_t smem_u32(const void* p) {
    uint32_t a;
    asm("{ .reg .u64 t; cvta.to.shared.u64 t, %1; cvt.u32.u64 %0, t; }"
        : "=r"(a) : "l"(p));
    return a;
}
__device__ __forceinline__ void cp_async16(uint32_t saddr, const void* gaddr) {
    asm volatile("cp.async.cg.shared.global [%0], [%1], 16;"
                 :: "r"(saddr), "l"(gaddr) : "memory");
}
__device__ __forceinline__ void cp_commit() {
    asm volatile("cp.async.commit_group;" ::: "memory");
}
__device__ __forceinline__ void cp_wait1() {
    asm volatile("cp.async.wait_group 1;" ::: "memory");
}
__device__ __forceinline__ void cp_wait0() {
    asm volatile("cp.async.wait_group 0;" ::: "memory");
}

__device__ __forceinline__ void mma_tf32(float& c0, float& c1, float& c2, float& c3,
                                         uint32_t a0, uint32_t a1, uint32_t a2, uint32_t a3,
                                         uint32_t b0, uint32_t b1) {
    asm volatile(
        "mma.sync.aligned.m16n8k8.row.col.f32.tf32.tf32.f32 "
        "{%0,%1,%2,%3}, {%4,%5,%6,%7}, {%8,%9}, {%0,%1,%2,%3};"
        : "+f"(c0), "+f"(c1), "+f"(c2), "+f"(c3)
        : "r"(a0), "r"(a1), "r"(a2), "r"(a3), "r"(b0), "r"(b1));
}
__device__ __forceinline__ void mma_bf16(float& c0, float& c1, float& c2, float& c3,
                                         uint32_t a0, uint32_t a1, uint32_t a2, uint32_t a3,
                                         uint32_t b0, uint32_t b1) {
    asm volatile(
        "mma.sync.aligned.m16n8k16.row.col.f32.bf16.bf16.f32 "
        "{%0,%1,%2,%3}, {%4,%5,%6,%7}, {%8,%9}, {%0,%1,%2,%3};"
        : "+f"(c0), "+f"(c1), "+f"(c2), "+f"(c3)
        : "r"(a0), "r"(a1), "r"(a2), "r"(a3), "r"(b0), "r"(b1));
}

__device__ __forceinline__ float tf32_rna(float f) {
    uint32_t h;
    asm("cvt.rna.tf32.f32 %0, %1;" : "=r"(h) : "f"(f));
    return __uint_as_float(h);
}

// ---------------------------------------------------------------------------
// Prep: fp32 -> planar bf16 {hi, lo}. Single merged launch over x, W_qkv,
// W_out (selected by index range).
// ---------------------------------------------------------------------------
#define N4_X  (NT_ * D_ / 4)
#define N4_WQ (3 * D_ * D_ / 4)
#define N4_WO (D_ * D_ / 4)
#define N4_TOTAL (N4_X + N4_WQ + N4_WO)

__global__ void split_all_kernel(const float4* __restrict__ x,
                                 const float4* __restrict__ wq,
                                 const float4* __restrict__ wo,
                                 __nv_bfloat162* __restrict__ xh,
                                 __nv_bfloat162* __restrict__ xl,
                                 __nv_bfloat162* __restrict__ wqh,
                                 __nv_bfloat162* __restrict__ wql,
                                 __nv_bfloat162* __restrict__ woh,
                                 __nv_bfloat162* __restrict__ wol)
{
    int i = blockIdx.x * blockDim.x + threadIdx.x;
    if (i >= N4_TOTAL) return;
    const float4* in;
    __nv_bfloat162 *hi, *lo;
    int j;
    if (i < N4_X)            { in = x;  hi = xh;  lo = xl;  j = i; }
    else if (i < N4_X + N4_WQ) { in = wq; hi = wqh; lo = wql; j = i - N4_X; }
    else                     { in = wo; hi = woh; lo = wol; j = i - N4_X - N4_WQ; }

    float4 v = in[j];
    __nv_bfloat16 h0 = __float2bfloat16(v.x);
    __nv_bfloat16 h1 = __float2bfloat16(v.y);
    __nv_bfloat16 h2 = __float2bfloat16(v.z);
    __nv_bfloat16 h3 = __float2bfloat16(v.w);
    hi[2 * j + 0] = __nv_bfloat162(h0, h1);
    hi[2 * j + 1] = __nv_bfloat162(h2, h3);
    lo[2 * j + 0] = __nv_bfloat162(
        __float2bfloat16(v.x - __bfloat162float(h0)),
        __float2bfloat16(v.y - __bfloat162float(h1)));
    lo[2 * j + 1] = __nv_bfloat162(
        __float2bfloat16(v.z - __bfloat162float(h2)),
        __float2bfloat16(v.w - __bfloat162float(h3)));
}

// ---------------------------------------------------------------------------
// bf16x3 GEMM (R14 config — 8 warps, 64x32 warp tile, 2 CTAs/SM).
// ---------------------------------------------------------------------------
#define PADB 40
#define PLANE_ELEMS (128 * PADB)
#define STAGEB (4 * PLANE_ELEMS)
#define GK_SMEM_BYTES (2 * STAGEB * 2)   // 81920 B

__global__ __launch_bounds__(256, 2) void gemm_bf16_kernel(
    const __nv_bfloat16* __restrict__ Ah, const __nv_bfloat16* __restrict__ Al,
    const __nv_bfloat16* __restrict__ Bh, const __nv_bfloat16* __restrict__ Bl,
    float* __restrict__ C,
    __nv_bfloat16* __restrict__ qh, __nv_bfloat16* __restrict__ ql,
    __nv_bfloat16* __restrict__ kh, __nv_bfloat16* __restrict__ kl,
    float* __restrict__ vo,
    int M, int N, int K, int mode)
{
    extern __shared__ __nv_bfloat16 smb[];

    const int t    = threadIdx.x;
    const int wid  = t >> 5;
    const int lane = t & 31;
    const int g    = lane >> 2;
    const int c4   = lane & 3;
    const int m0   = blockIdx.y * 128;
    const int n0   = blockIdx.x * 128;
    const int wm   = (wid & 1) * 64;
    const int wn   = (wid >> 1) * 32;

    float acc[4][4][4] = {};
    const int nchunks = K >> 5;

    const __nv_bfloat16* planes[4] = {Ah, Al, Bh, Bl};

    #define LOAD_CHUNK(cc)                                                    \
    {                                                                         \
        const int s_  = (cc) & 1;                                             \
        const int k0_ = (cc) * 32;                                            \
        const uint32_t base_ = smem_u32(smb) + s_ * STAGEB * 2;               \
        _Pragma("unroll")                                                     \
        for (int u = 0; u < 8; u++) {                                         \
            const int pl  = u >> 1;                                           \
            const int rem = ((u & 1) << 8) + t;                               \
            const int row = rem >> 2;                                         \
            const int grp = rem & 3;                                          \
            const int mr  = (pl < 2 ? m0 : n0) + row;                         \
            cp_async16(base_ + (pl * PLANE_ELEMS + row * PADB + grp * 8) * 2, \
                       planes[pl] + (size_t)mr * K + k0_ + grp * 8);          \
        }                                                                     \
        cp_commit();                                                          \
    }

    LOAD_CHUNK(0);

    for (int c = 0; c < nchunks; c++) {
        if (c + 1 < nchunks) {
            LOAD_CHUNK(c + 1);
            cp_wait1();
        } else {
            cp_wait0();
        }
        __syncthreads();

        const uint32_t* S = (const uint32_t*)(smb + (c & 1) * STAGEB);
        const uint32_t* AhU = S;
        const uint32_t* AlU = S + PLANE_ELEMS / 2;
        const uint32_t* BhU = S + PLANE_ELEMS;
        const uint32_t* BlU = S + 3 * PLANE_ELEMS / 2;

        #pragma unroll
        for (int kk = 0; kk < 32; kk += 16) {
            const int ko2 = (kk >> 1) + c4;
            uint32_t ah[4][4], al[4][4], bhf[4][2], blf[4][2];
            #pragma unroll
            for (int mi = 0; mi < 4; mi++) {
                const int r = (wm + mi * 16 + g) * 20 + ko2;
                ah[mi][0] = AhU[r];          al[mi][0] = AlU[r];
                ah[mi][1] = AhU[r + 160];    al[mi][1] = AlU[r + 160];
                ah[mi][2] = AhU[r + 4];      al[mi][2] = AlU[r + 4];
                ah[mi][3] = AhU[r + 164];    al[mi][3] = AlU[r + 164];
            }
            #pragma unroll
            for (int ni = 0; ni < 4; ni++) {
                const int r = (wn + ni * 8 + g) * 20 + ko2;
                bhf[ni][0] = BhU[r];     blf[ni][0] = BlU[r];
                bhf[ni][1] = BhU[r + 4]; blf[ni][1] = BlU[r + 4];
            }
            #pragma unroll
            for (int mi = 0; mi < 4; mi++)
                #pragma unroll
                for (int ni = 0; ni < 4; ni++)
                    mma_bf16(acc[mi][ni][0], acc[mi][ni][1],
                             acc[mi][ni][2], acc[mi][ni][3],
                             ah[mi][0], ah[mi][1], ah[mi][2], ah[mi][3],
                             blf[ni][0], blf[ni][1]);
            #pragma unroll
            for (int mi = 0; mi < 4; mi++)
                #pragma unroll
                for (int ni = 0; ni < 4; ni++)
                    mma_bf16(acc[mi][ni][0], acc[mi][ni][1],
                             acc[mi][ni][2], acc[mi][ni][3],
                             al[mi][0], al[mi][1], al[mi][2], al[mi][3],
                             bhf[ni][0], bhf[ni][1]);
            #pragma unroll
            for (int mi = 0; mi < 4; mi++)
                #pragma unroll
                for (int ni = 0; ni < 4; ni++)
                    mma_bf16(acc[mi][ni][0], acc[mi][ni][1],
                             acc[mi][ni][2], acc[mi][ni][3],
                             ah[mi][0], ah[mi][1], ah[mi][2], ah[mi][3],
                             bhf[ni][0], bhf[ni][1]);
        }
        __syncthreads();
    }
    #undef LOAD_CHUNK

    #pragma unroll
    for (int mi = 0; mi < 4; mi++) {
        #pragma unroll
        for (int half = 0; half < 2; half++) {
            const int m = m0 + wm + mi * 16 + g + half * 8;
            if (mode == 0) {
                #pragma unroll
                for (int ni = 0; ni < 4; ni++) {
                    int n = n0 + wn + ni * 8 + c4 * 2;
                    float2 v = half == 0
                        ? make_float2(acc[mi][ni][0], acc[mi][ni][1])
                        : make_float2(acc[mi][ni][2], acc[mi][ni][3]);
                    *(float2*)(C + (size_t)m * N + n) = v;
                }
            } else {
                const int b = m >> 11;
                const int l = m & 2047;
                #pragma unroll
                for (int ni = 0; ni < 4; ni++) {
                    int n     = n0 + wn + ni * 8 + c4 * 2;
                    int which = n >> 10;
                    int rem   = n & 1023;
                    int h     = rem >> 6;
                    int d     = rem & 63;
                    int bh_i  = b * H_ + h;
                    float v0 = half == 0 ? acc[mi][ni][0] : acc[mi][ni][2];
                    float v1 = half == 0 ? acc[mi][ni][1] : acc[mi][ni][3];
                    if (which == 2) {
                        size_t idx = ((size_t)bh_i * HD_ + d) * L_ + l;
                        vo[idx]      = tf32_rna(v0);
                        vo[idx + L_] = tf32_rna(v1);
                    } else {
                        size_t idx = ((size_t)bh_i * L_ + l) * HD_ + d;
                        __nv_bfloat16 h0 = __float2bfloat16(v0);
                        __nv_bfloat16 h1 = __float2bfloat16(v1);
                        __nv_bfloat162 hi2(h0, h1);
                        __nv_bfloat162 lo2(
                            __float2bfloat16(v0 - __bfloat162float(h0)),
                            __float2bfloat16(v1 - __bfloat162float(h1)));
                        if (which == 0) {
                            *(__nv_bfloat162*)(qh + idx) = hi2;
                            *(__nv_bfloat162*)(ql + idx) = lo2;
                        } else {
                            *(__nv_bfloat162*)(kh + idx) = hi2;
                            *(__nv_bfloat162*)(kl + idx) = lo2;
                        }
                    }
                }
            }
        }
    }
}

// ---------------------------------------------------------------------------
// Flash attention (R14): S=QK^T bf16x3, P*V 1xTF32.
// cp.async DOUBLE-BUFFERED K/V tiles, 2 CTAs/SM (107.5 KB smem).
// ---------------------------------------------------------------------------
#define KPAD 72                      // bf16 per row (64 + 8) = 36 u32
#define APAD 68                      // f32 per row
#define KPLANE (64 * KPAD)           // bf16 elems per K plane
#define VPLANE (64 * APAD)           // f32 elems per V tile
#define ATT_STAGE_BYTES (2 * KPLANE * 2 + VPLANE * 4)       // 35840 B
#define ATT_SMEM_BYTES (2 * KPLANE * 2 + VPLANE * 4 \
                        + 2 * ATT_STAGE_BYTES)               // 107520 B

__global__ __launch_bounds__(128, 2) void attn_tc_kernel(
    const __nv_bfloat16* __restrict__ qh, const __nv_bfloat16* __restrict__ ql,
    const __nv_bfloat16* __restrict__ kh, const __nv_bfloat16* __restrict__ kl,
    const float* __restrict__ vt,
    __nv_bfloat16* __restrict__ ch, __nv_bfloat16* __restrict__ cl)
{
    const int qt = (int)gridDim.x - 1 - (int)blockIdx.x;
    const int bh = blockIdx.y;

    extern __shared__ char smc[];
    __nv_bfloat16* Qh = (__nv_bfloat16*)smc;            // KPLANE bf16
    __nv_bfloat16* Ql = Qh + KPLANE;                    // KPLANE bf16
    float* Ss = (float*)(Ql + KPLANE);                  // VPLANE f32
    char*  stage_base = (char*)(Ss + VPLANE);           // 2 x ATT_STAGE_BYTES

    const int t    = threadIdx.x;
    const int w    = t >> 5;
    const int lane = t & 31;
    const int g    = lane >> 2;
    const int c4   = lane & 3;
    const int q0   = w * 16;

    const __nv_bfloat16* Qhg = qh + ((size_t)bh * L_ + (size_t)qt * 64) * HD_;
    const __nv_bfloat16* Qlg = ql + ((size_t)bh * L_ + (size_t)qt * 64) * HD_;
    const __nv_bfloat16* Khg = kh + ((size_t)bh * L_) * HD_;
    const __nv_bfloat16* Klg = kl + ((size_t)bh * L_) * HD_;
    const float*         Vg  = vt + ((size_t)bh * HD_) * L_;

    // Load Q tiles (plain loads; covered by first barrier)
    #pragma unroll
    for (int u = 0; u < 4; u++) {
        int idx = t + u * 128;
        int row = idx >> 3;
        int cg  = idx & 7;
        *(uint4*)&Qh[row * KPAD + cg * 8] =
            *(const uint4*)(Qhg + (size_t)row * HD_ + cg * 8);
        *(uint4*)&Ql[row * KPAD + cg * 8] =
            *(const uint4*)(Qlg + (size_t)row * HD_ + cg * 8);
    }

    #define LOAD_TILE(kt_)                                                    \
    {                                                                         \
        const uint32_t sb_ = smem_u32(stage_base) +                           \
                             ((kt_) & 1) * ATT_STAGE_BYTES;                   \
        const uint32_t sKh_ = sb_;                                            \
        const uint32_t sKl_ = sb_ + KPLANE * 2;                               \
        const uint32_t sV_  = sb_ + 2 * KPLANE * 2;                           \
        _Pragma("unroll")                                                     \
        for (int u = 0; u < 4; u++) {                                         \
            int idx = t + u * 128;                                            \
            int row = idx >> 3;                                               \
            int cg  = idx & 7;                                                \
            cp_async16(sKh_ + (row * KPAD + cg * 8) * 2,                      \
                       Khg + ((size_t)((kt_) * 64 + row)) * HD_ + cg * 8);    \
            cp_async16(sKl_ + (row * KPAD + cg * 8) * 2,                      \
                       Klg + ((size_t)((kt_) * 64 + row)) * HD_ + cg * 8);    \
        }                                                                     \
        _Pragma("unroll")                                                     \
        for (int u = 0; u < 8; u++) {                                         \
            int idx = t + u * 128;                                            \
            int row = idx >> 4;                                               \
            int cg  = idx & 15;                                               \
            cp_async16(sV_ + (row * APAD + cg * 4) * 4,                       \
                       Vg + (size_t)row * L_ + (kt_) * 64 + cg * 4);          \
        }                                                                     \
        cp_commit();                                                          \
    }

    LOAD_TILE(0);

    float m0r = -1.0e30f, m1r = -1.0e30f;
    float l0r = 0.0f,     l1r = 0.0f;
    float oacc[8][4] = {};

    for (int kt = 0; kt <= qt; kt++) {
        __syncthreads();   // all warps done with stage (kt+1)&1 (iter kt-1)

        if (kt + 1 <= qt) {
            LOAD_TILE(kt + 1);
            cp_wait1();    // tile kt landed (own groups)
        } else {
            cp_wait0();
        }
        __syncthreads();   // tile kt visible to all warps

        const char* sb = stage_base + (kt & 1) * ATT_STAGE_BYTES;
        const uint32_t* KhU = (const uint32_t*)sb;
        const uint32_t* KlU = KhU + KPLANE / 2;
        const float*    Vts = (const float*)(sb + 2 * KPLANE * 2);

        // ---- S = Q K^T (bf16x3, term-major) ----
        float sacc[8][4] = {};
        const uint32_t* QhU = (const uint32_t*)Qh;
        const uint32_t* QlU = (const uint32_t*)Ql;
        #pragma unroll
        for (int kk = 0; kk < 64; kk += 16) {
            const int ko2 = (kk >> 1) + c4;
            uint32_t ah[4], al[4], kbh[8][2], kbl[8][2];
            {
                const int r = (q0 + g) * 36 + ko2;
                ah[0] = QhU[r];          al[0] = QlU[r];
                ah[1] = QhU[r + 288];    al[1] = QlU[r + 288];
                ah[2] = QhU[r + 4];      al[2] = QlU[r + 4];
                ah[3] = QhU[r + 292];    al[3] = QlU[r + 292];
            }
            #pragma unroll
            for (int ni = 0; ni < 8; ni++) {
                const int r = (ni * 8 + g) * 36 + ko2;
                kbh[ni][0] = KhU[r];     kbl[ni][0] = KlU[r];
                kbh[ni][1] = KhU[r + 4]; kbl[ni][1] = KlU[r + 4];
            }
            #pragma unroll
            for (int ni = 0; ni < 8; ni++)
                mma_bf16(sacc[ni][0], sacc[ni][1], sacc[ni][2], sacc[ni][3],
                         ah[0], ah[1], ah[2], ah[3], kbl[ni][0], kbl[ni][1]);
            #pragma unroll
            for (int ni = 0; ni < 8; ni++)
                mma_bf16(sacc[ni][0], sacc[ni][1], sacc[ni][2], sacc[ni][3],
                         al[0], al[1], al[2], al[3], kbh[ni][0], kbh[ni][1]);
            #pragma unroll
            for (int ni = 0; ni < 8; ni++)
                mma_bf16(sacc[ni][0], sacc[ni][1], sacc[ni][2], sacc[ni][3],
                         ah[0], ah[1], ah[2], ah[3], kbh[ni][0], kbh[ni][1]);
        }

        // ---- scale + causal mask ----
        const int qrow0 = qt * 64 + q0 + g;
        const int qrow1 = qrow0 + 8;
        #pragma unroll
        for (int ni = 0; ni < 8; ni++) {
            int col0 = kt * 64 + ni * 8 + c4 * 2;
            int col1 = col0 + 1;
            sacc[ni][0] = (col0 <= qrow0) ? sacc[ni][0] * 0.125f : -1.0e30f;
            sacc[ni][1] = (col1 <= qrow0) ? sacc[ni][1] * 0.125f : -1.0e30f;
            sacc[ni][2] = (col0 <= qrow1) ? sacc[ni][2] * 0.125f : -1.0e30f;
            sacc[ni][3] = (col1 <= qrow1) ? sacc[ni][3] * 0.125f : -1.0e30f;
        }

        // ---- online softmax ----
        float mx0 = -1.0e30f, mx1 = -1.0e30f;
        #pragma unroll
        for (int ni = 0; ni < 8; ni++) {
            mx0 = fmaxf(mx0, fmaxf(sacc[ni][0], sacc[ni][1]));
            mx1 = fmaxf(mx1, fmaxf(sacc[ni][2], sacc[ni][3]));
        }
        mx0 = fmaxf(mx0, __shfl_xor_sync(0xffffffffu, mx0, 1));
        mx0 = fmaxf(mx0, __shfl_xor_sync(0xffffffffu, mx0, 2));
        mx1 = fmaxf(mx1, __shfl_xor_sync(0xffffffffu, mx1, 1));
        mx1 = fmaxf(mx1, __shfl_xor_sync(0xffffffffu, mx1, 2));

        float mn0 = fmaxf(m0r, mx0);
        float mn1 = fmaxf(m1r, mx1);
        float corr0 = __expf(m0r - mn0);
        float corr1 = __expf(m1r - mn1);
        m0r = mn0; m1r = mn1;

        float sum0 = 0.0f, sum1 = 0.0f;
        #pragma unroll
        for (int ni = 0; ni < 8; ni++) {
            sacc[ni][0] = __expf(sacc[ni][0] - mn0); sum0 += sacc[ni][0];
            sacc[ni][1] = __expf(sacc[ni][1] - mn0); sum0 += sacc[ni][1];
            sacc[ni][2] = __expf(sacc[ni][2] - mn1); sum1 += sacc[ni][2];
            sacc[ni][3] = __expf(sacc[ni][3] - mn1); sum1 += sacc[ni][3];
        }
        sum0 += __shfl_xor_sync(0xffffffffu, sum0, 1);
        sum0 += __shfl_xor_sync(0xffffffffu, sum0, 2);
        sum1 += __shfl_xor_sync(0xffffffffu, sum1, 1);
        sum1 += __shfl_xor_sync(0xffffffffu, sum1, 2);
        l0r = l0r * corr0 + sum0;
        l1r = l1r * corr1 + sum1;

        #pragma unroll
        for (int ni = 0; ni < 8; ni++) {
            oacc[ni][0] *= corr0; oacc[ni][1] *= corr0;
            oacc[ni][2] *= corr1; oacc[ni][3] *= corr1;
        }

        // ---- stage P (tf32-rounded; own warp rows only) ----
        #pragma unroll
        for (int ni = 0; ni < 8; ni++) {
            *(float2*)&Ss[(q0 + g    ) * APAD + ni * 8 + c4 * 2] =
                make_float2(tf32_rna(sacc[ni][0]), tf32_rna(sacc[ni][1]));
            *(float2*)&Ss[(q0 + g + 8) * APAD + ni * 8 + c4 * 2] =
                make_float2(tf32_rna(sacc[ni][2]), tf32_rna(sacc[ni][3]));
        }
        __syncwarp();

        // ---- O += P V (1xTF32) ----
        const uint32_t* Pu = (const uint32_t*)Ss;
        const uint32_t* Vu = (const uint32_t*)Vts;
        #pragma unroll
        for (int kk = 0; kk < 64; kk += 8) {
            uint32_t a0, a1, a2, a3;
            {
                const uint32_t* base = Pu + (q0 + g) * APAD + kk + c4;
                a0 = base[0];
                a1 = base[8 * APAD];
                a2 = base[4];
                a3 = base[8 * APAD + 4];
            }
            #pragma unroll
            for (int ni = 0; ni < 8; ni++) {
                const uint32_t* base = Vu + (ni * 8 + g) * APAD + kk + c4;
                uint32_t b0 = base[0];
                uint32_t b1 = base[4];
                mma_tf32(oacc[ni][0], oacc[ni][1], oacc[ni][2], oacc[ni][3],
                         a0, a1, a2, a3, b0, b1);
            }
        }
    }
    #undef LOAD_TILE

    // ---- normalize + write ctx planar bf16 ----
    const int b = bh >> 4;
    const int h = bh & 15;
    const float inv0 = 1.0f / l0r;
    const float inv1 = 1.0f / l1r;
    const int l0i = qt * 64 + q0 + g;
    const int l1i = l0i + 8;
    #pragma unroll
    for (int ni = 0; ni < 8; ni++) {
        int d = ni * 8 + c4 * 2;
        size_t i0 = (((size_t)b * L_ + l0i) * H_ + h) * HD_ + d;
        size_t i1 = (((size_t)b * L_ + l1i) * H_ + h) * HD_ + d;
        float o00 = oacc[ni][0] * inv0, o01 = oacc[ni][1] * inv0;
        float o10 = oacc[ni][2] * inv1, o11 = oacc[ni][3] * inv1;
        __nv_bfloat16 h00 = __float2bfloat16(o00);
        __nv_bfloat16 h01 = __float2bfloat16(o01);
        __nv_bfloat16 h10 = __float2bfloat16(o10);
        __nv_bfloat16 h11 = __float2bfloat16(o11);
        *(__nv_bfloat162*)(ch + i0) = __nv_bfloat162(h00, h01);
        *(__nv_bfloat162*)(ch + i1) = __nv_bfloat162(h10, h11);
        *(__nv_bfloat162*)(cl + i0) = __nv_bfloat162(
            __float2bfloat16(o00 - __bfloat162float(h00)),
            __float2bfloat16(o01 - __bfloat162float(h01)));
        *(__nv_bfloat162*)(cl + i1) = __nv_bfloat162(
            __float2bfloat16(o10 - __bfloat162float(h10)),
            __float2bfloat16(o11 - __bfloat162float(h11)));
    }
}

// ---------------------------------------------------------------------------
extern "C" void kernel_launch(void* const* d_in, const int* in_sizes, int n_in,
                              void* d_out, int out_size)
{
    const float* x     = (const float*)d_in[0];
    const float* W_qkv = (const float*)d_in[1];
    const float* W_out = (const float*)d_in[2];
    float* out = (float*)d_out;

    __nv_bfloat16 *xh, *xl, *wqh, *wql, *woh, *wol, *ctxh, *ctxl;
    __nv_bfloat16 *qhp, *qlp, *khp, *klp;
    float *vtp;
    cudaGetSymbolAddress((void**)&xh,   g_xh);
    cudaGetSymbolAddress((void**)&xl,   g_xl);
    cudaGetSymbolAddress((void**)&wqh,  g_wqh);
    cudaGetSymbolAddress((void**)&wql,  g_wql);
    cudaGetSymbolAddress((void**)&woh,  g_woh);
    cudaGetSymbolAddress((void**)&wol,  g_wol);
    cudaGetSymbolAddress((void**)&ctxh, g_ctxh);
    cudaGetSymbolAddress((void**)&ctxl, g_ctxl);
    cudaGetSymbolAddress((void**)&qhp,  g_qh);
    cudaGetSymbolAddress((void**)&qlp,  g_ql);
    cudaGetSymbolAddress((void**)&khp,  g_kh);
    cudaGetSymbolAddress((void**)&klp,  g_kl);
    cudaGetSymbolAddress((void**)&vtp,  g_vt);

    cudaFuncSetAttribute(gemm_bf16_kernel,
                         cudaFuncAttributeMaxDynamicSharedMemorySize, GK_SMEM_BYTES);
    cudaFuncSetAttribute(attn_tc_kernel,
                         cudaFuncAttributeMaxDynamicSharedMemorySize, ATT_SMEM_BYTES);

    // 0) planar bf16 splits of all inputs (single merged launch)
    split_all_kernel<<<(N4_TOTAL + 255) / 256, 256>>>(
        (const float4*)x, (const float4*)W_qkv, (const float4*)W_out,
        (__nv_bfloat162*)xh,  (__nv_bfloat162*)xl,
        (__nv_bfloat162*)wqh, (__nv_bfloat162*)wql,
        (__nv_bfloat162*)woh, (__nv_bfloat162*)wol);

    // 1) QKV projection (bf16x3) -> q/k planar bf16, v^T tf32 fp32
    gemm_bf16_kernel<<<dim3(3 * D_ / 128, NT_ / 128), 256, GK_SMEM_BYTES>>>(
        xh, xl, wqh, wql, nullptr, qhp, qlp, khp, klp, vtp, NT_, 3 * D_, D_, 1);

    // 2) causal flash attention (pipelined K/V; S bf16x3, PV 1xTF32)
    attn_tc_kernel<<<dim3(L_ / 64, BH_), 128, ATT_SMEM_BYTES>>>(
        qhp, qlp, khp, klp, vtp, ctxh, ctxl);

    // 3) output projection (bf16x3)
    gemm_bf16_kernel<<<dim3(D_ / 128, NT_ / 128), 256, GK_SMEM_BYTES>>>(
        ctxh, ctxl, woh, wol, out, nullptr, nullptr, nullptr, nullptr, nullptr,
        NT_, D_, D_, 0);
}